// round 13
// baseline (speedup 1.0000x reference)
#include <cuda_runtime.h>
#include <cuda_bf16.h>
#include <cstdint>

// MissHitScatter: inputs [N=65536, D=1024] f32 -> out [P=4, N, D] f32.
// slice 0 = copy of input, slices 1..3 = zeros. 1.25 GiB total traffic.
//
// R12: champion schedule (contiguous 32 KB per-block spans, batched loads
// before streaming stores, copy blocks front-loaded) with Blackwell 256-bit
// memory ops: ld.global.nc.v8.f32 / st.global.wt.v8.f32 (32 B per lane,
// 1 KB contiguous per warp instruction, half the LSU instruction count).

#define V 4  // float8 (32 B) per thread per kernel: 4 x 32 B = 128 B/thread

__device__ __forceinline__ void ldg_nc_v8(float* v, const float* p) {
    asm volatile(
        "ld.global.nc.v8.f32 {%0,%1,%2,%3,%4,%5,%6,%7}, [%8];"
        : "=f"(v[0]), "=f"(v[1]), "=f"(v[2]), "=f"(v[3]),
          "=f"(v[4]), "=f"(v[5]), "=f"(v[6]), "=f"(v[7])
        : "l"(p));
}

__device__ __forceinline__ void stg_wt_v8(float* p, const float* v) {
    asm volatile(
        "st.global.wt.v8.f32 [%0], {%1,%2,%3,%4,%5,%6,%7,%8};"
        :: "l"(p),
           "f"(v[0]), "f"(v[1]), "f"(v[2]), "f"(v[3]),
           "f"(v[4]), "f"(v[5]), "f"(v[6]), "f"(v[7])
        : "memory");
}

__global__ void __launch_bounds__(256) misshit_scatter_kernel(
    const float* __restrict__ in, float* __restrict__ out, size_t n8)
{
    // Index space: float8 (32 B) units. Block covers 256*V float8 = 32 KB,
    // warp-coalesced within each sub-iteration (stride = blockDim float8).
    size_t base = (size_t)blockIdx.x * (blockDim.x * V) + threadIdx.x;

    if (base + (size_t)(V - 1) * blockDim.x < n8) {
        // Pure copy block: batch all loads first (MLP=V), then stream stores.
        float v[V][8];
#pragma unroll
        for (int j = 0; j < V; j++)
            ldg_nc_v8(v[j], in + (base + (size_t)j * blockDim.x) * 8);
#pragma unroll
        for (int j = 0; j < V; j++)
            stg_wt_v8(out + (base + (size_t)j * blockDim.x) * 8, v[j]);
    } else if (base >= n8) {
        // Pure zero block: streaming stores only.
        float z[8] = {0.f, 0.f, 0.f, 0.f, 0.f, 0.f, 0.f, 0.f};
#pragma unroll
        for (int j = 0; j < V; j++)
            stg_wt_v8(out + (base + (size_t)j * blockDim.x) * 8, z);
    } else {
        // Straddle (not taken for this shape: n8 = 8Mi is a multiple of 1024).
        float z[8] = {0.f, 0.f, 0.f, 0.f, 0.f, 0.f, 0.f, 0.f};
#pragma unroll
        for (int j = 0; j < V; j++) {
            size_t i = base + (size_t)j * blockDim.x;
            if (i < n8) {
                float v[8];
                ldg_nc_v8(v, in + i * 8);
                stg_wt_v8(out + i * 8, v);
            } else {
                stg_wt_v8(out + i * 8, z);
            }
        }
    }
}

extern "C" void kernel_launch(void* const* d_in, const int* in_sizes, int n_in,
                              void* d_out, int out_size) {
    const size_t n_elems = (size_t)in_sizes[0];   // 65536 * 1024 floats
    const size_t n8 = n_elems / 8;                // float8 per slice (8Mi)
    const size_t total8 = n8 * 4;                 // float8 in full output

    const int threads = 256;
    const size_t per_block = (size_t)threads * V; // 1024 float8 = 32 KB
    const int blocks = (int)((total8 + per_block - 1) / per_block);  // 32768

    misshit_scatter_kernel<<<blocks, threads>>>(
        (const float*)d_in[0], (float*)d_out, n8);
}